// round 1
// baseline (speedup 1.0000x reference)
#include <cuda_runtime.h>
#include <cstdint>
#include <cstddef>

// Problem constants
#define B_   8
#define N_   4096
#define C_   256
#define CI_  32
#define BM   64
#define BN   64
#define TSTR 68   // padded row stride (floats) for transposed k-major tiles

// Scratch (static device globals — no runtime allocation allowed)
__device__ float g_q[B_ * N_ * CI_];
__device__ float g_k[B_ * N_ * CI_];
__device__ float g_v[B_ * N_ * CI_];

// ---------------- packed fp32x2 helpers (Blackwell FFMA2 path) ----------------
__device__ __forceinline__ uint64_t pk2(float lo, float hi) {
    uint64_t r; asm("mov.b64 %0,{%1,%2};" : "=l"(r) : "f"(lo), "f"(hi)); return r;
}
__device__ __forceinline__ uint64_t bc2(float v) { return pk2(v, v); }
__device__ __forceinline__ void up2(uint64_t p, float &lo, float &hi) {
    asm("mov.b64 {%0,%1},%2;" : "=f"(lo), "=f"(hi) : "l"(p));
}
__device__ __forceinline__ uint64_t f2fma(uint64_t a, uint64_t b, uint64_t c) {
    uint64_t d; asm("fma.rn.f32x2 %0,%1,%2,%3;" : "=l"(d) : "l"(a), "l"(b), "l"(c)); return d;
}
__device__ __forceinline__ uint64_t f2mul(uint64_t a, uint64_t b) {
    uint64_t d; asm("mul.rn.f32x2 %0,%1,%2;" : "=l"(d) : "l"(a), "l"(b)); return d;
}

// ---------------- Kernel 1: fused channel projections (1x1 convs) ----------------
// grid.x: 512 row-tiles of 64 rows over B*N = 32768 rows; grid.y: {q,k,v}
__global__ void __launch_bounds__(256, 2) proj_kernel(
    const float* __restrict__ x, const float* __restrict__ y,
    const float* __restrict__ Wfy, const float* __restrict__ Wgx,
    const float* __restrict__ Whx)
{
    __shared__ float sA[32 * TSTR];  // A^T chunk: [k][row]
    __shared__ float sW[32 * 32];    // W chunk:   [k][col]

    const int tid = threadIdx.x;
    const int tx  = tid & 15;
    const int ty  = tid >> 4;

    const float* A; const float* W; float* out;
    if (blockIdx.y == 0)      { A = y; W = Wfy; out = g_q; }
    else if (blockIdx.y == 1) { A = x; W = Wgx; out = g_k; }
    else                      { A = x; W = Whx; out = g_v; }

    const int row0 = blockIdx.x * BM;

    uint64_t acc[4] = {0ull, 0ull, 0ull, 0ull};  // 4 rows x (2 packed cols)

    for (int kc = 0; kc < C_; kc += 32) {
        __syncthreads();
        // Load A chunk transposed: 64 rows x 32 k  -> sA[k][row]
        #pragma unroll
        for (int t = 0; t < 8; t++) {
            int idx = tid + t * 256;
            int r = idx >> 5;
            int k = idx & 31;
            sA[k * TSTR + r] = A[(size_t)(row0 + r) * C_ + kc + k];
        }
        // Load W chunk: 32 k x 32 cols
        #pragma unroll
        for (int t = 0; t < 4; t++) {
            int idx = tid + t * 256;
            int kr = idx >> 5;
            int c = idx & 31;
            sW[kr * 32 + c] = W[(size_t)(kc + kr) * CI_ + c];
        }
        __syncthreads();

        #pragma unroll 8
        for (int k = 0; k < 32; k++) {
            float4 a4 = *(const float4*)&sA[k * TSTR + ty * 4];
            uint64_t b = *(const uint64_t*)&sW[k * 32 + 2 * tx];
            acc[0] = f2fma(bc2(a4.x), b, acc[0]);
            acc[1] = f2fma(bc2(a4.y), b, acc[1]);
            acc[2] = f2fma(bc2(a4.z), b, acc[2]);
            acc[3] = f2fma(bc2(a4.w), b, acc[3]);
        }
    }

    #pragma unroll
    for (int i = 0; i < 4; i++) {
        *(uint64_t*)&out[(size_t)(row0 + ty * 4 + i) * CI_ + 2 * tx] = acc[i];
    }
}

// ---------------- Kernel 2: flash attention + fused epilogue ----------------
// One CTA per (query-block of 64 rows, batch). 256 threads.
// Thread grid 16x16: rows ty*4..+4, S cols {2tx, 2tx+1, 2tx+32, 2tx+33}.
// Shared layout (floats), main phase:
//   sQ  [32][TSTR]  @ 0        (Q^T)
//   sK  [32][TSTR]  @ 2176     (K^T)
//   sV  [64][32]    @ 4352
//   sP  [64][TSTR]  @ 6400     (P^T: [key][row])
// Epilogue phase (overlaid):
//   sOt [32][TSTR]  @ 0        (O^T: [ci][row])
//   sWo [32][256]   @ 2176
__global__ void __launch_bounds__(256, 2) attn_kernel(
    const float* __restrict__ x, const float* __restrict__ Wout,
    const float* __restrict__ sigma_p, float* __restrict__ outp)
{
    __shared__ float smem[10752];  // 42 KB
    float* sQ  = smem;
    float* sK  = smem + 32 * TSTR;
    float* sV  = smem + 2 * 32 * TSTR;
    float* sP  = smem + 2 * 32 * TSTR + BN * CI_;
    float* sOt = smem;
    float* sWo = smem + 32 * TSTR;

    const int tid = threadIdx.x;
    const int tx  = tid & 15;
    const int ty  = tid >> 4;
    const int qb  = blockIdx.x;   // query block (0..63)
    const int b   = blockIdx.y;   // batch

    // Load Q tile transposed (once)
    const float* qbase = g_q + ((size_t)b * N_ + qb * BM) * CI_;
    #pragma unroll
    for (int t = 0; t < 8; t++) {
        int idx = tid + t * 256;
        int r = idx >> 5;
        int k = idx & 31;
        sQ[k * TSTR + r] = qbase[r * CI_ + k];
    }

    float m_run[4], l_run[4];
    uint64_t oacc[4];  // O: 4 rows x (cols 2tx,2tx+1 packed)
    #pragma unroll
    for (int i = 0; i < 4; i++) { m_run[i] = -1e30f; l_run[i] = 0.0f; oacc[i] = 0ull; }

    for (int kb = 0; kb < N_; kb += BN) {
        __syncthreads();  // previous iteration's P/V reads done
        // Load K tile transposed
        const float* kbase = g_k + ((size_t)b * N_ + kb) * CI_;
        #pragma unroll
        for (int t = 0; t < 8; t++) {
            int idx = tid + t * 256;
            int r = idx >> 5;
            int k = idx & 31;
            sK[k * TSTR + r] = kbase[r * CI_ + k];
        }
        // Load V tile (row-major [key][ci])
        const float4* vbase = (const float4*)(g_v + ((size_t)b * N_ + kb) * CI_);
        #pragma unroll
        for (int t = 0; t < 2; t++) {
            ((float4*)sV)[tid + t * 256] = vbase[tid + t * 256];
        }
        __syncthreads();

        // ---- S = Q K^T (64x64, k=32) ----
        uint64_t sacc[4][2];
        #pragma unroll
        for (int i = 0; i < 4; i++) { sacc[i][0] = 0ull; sacc[i][1] = 0ull; }
        #pragma unroll 8
        for (int k = 0; k < 32; k++) {
            float4 q4   = *(const float4*)&sQ[k * TSTR + ty * 4];
            uint64_t b0 = *(const uint64_t*)&sK[k * TSTR + 2 * tx];
            uint64_t b1 = *(const uint64_t*)&sK[k * TSTR + 2 * tx + 32];
            uint64_t a0 = bc2(q4.x), a1 = bc2(q4.y), a2 = bc2(q4.z), a3 = bc2(q4.w);
            sacc[0][0] = f2fma(a0, b0, sacc[0][0]); sacc[0][1] = f2fma(a0, b1, sacc[0][1]);
            sacc[1][0] = f2fma(a1, b0, sacc[1][0]); sacc[1][1] = f2fma(a1, b1, sacc[1][1]);
            sacc[2][0] = f2fma(a2, b0, sacc[2][0]); sacc[2][1] = f2fma(a2, b1, sacc[2][1]);
            sacc[3][0] = f2fma(a3, b0, sacc[3][0]); sacc[3][1] = f2fma(a3, b1, sacc[3][1]);
        }

        // ---- online softmax ----
        float s[4][4];
        #pragma unroll
        for (int i = 0; i < 4; i++) {
            up2(sacc[i][0], s[i][0], s[i][1]);
            up2(sacc[i][1], s[i][2], s[i][3]);
        }
        #pragma unroll
        for (int i = 0; i < 4; i++) {
            float rm = fmaxf(fmaxf(s[i][0], s[i][1]), fmaxf(s[i][2], s[i][3]));
            rm = fmaxf(rm, __shfl_xor_sync(0xffffffffu, rm, 8, 16));
            rm = fmaxf(rm, __shfl_xor_sync(0xffffffffu, rm, 4, 16));
            rm = fmaxf(rm, __shfl_xor_sync(0xffffffffu, rm, 2, 16));
            rm = fmaxf(rm, __shfl_xor_sync(0xffffffffu, rm, 1, 16));
            float mnew  = fmaxf(m_run[i], rm);
            float alpha = __expf(m_run[i] - mnew);
            m_run[i] = mnew;
            float ps = 0.0f;
            #pragma unroll
            for (int j = 0; j < 4; j++) {
                float p = __expf(s[i][j] - mnew);
                s[i][j] = p;
                ps += p;
            }
            ps += __shfl_xor_sync(0xffffffffu, ps, 8, 16);
            ps += __shfl_xor_sync(0xffffffffu, ps, 4, 16);
            ps += __shfl_xor_sync(0xffffffffu, ps, 2, 16);
            ps += __shfl_xor_sync(0xffffffffu, ps, 1, 16);
            l_run[i] = l_run[i] * alpha + ps;
            oacc[i]  = f2mul(oacc[i], bc2(alpha));
        }

        // ---- stage P^T[key][row] ----
        #pragma unroll
        for (int jj = 0; jj < 4; jj++) {
            int c = 2 * tx + (jj >> 1) * 32 + (jj & 1);
            float4 pv = make_float4(s[0][jj], s[1][jj], s[2][jj], s[3][jj]);
            *(float4*)&sP[c * TSTR + ty * 4] = pv;
        }
        __syncthreads();

        // ---- O += P V (64x32, k=64) ----
        #pragma unroll 8
        for (int kk = 0; kk < BN; kk++) {
            float4 p4   = *(const float4*)&sP[kk * TSTR + ty * 4];
            uint64_t v2 = *(const uint64_t*)&sV[kk * CI_ + 2 * tx];
            oacc[0] = f2fma(bc2(p4.x), v2, oacc[0]);
            oacc[1] = f2fma(bc2(p4.y), v2, oacc[1]);
            oacc[2] = f2fma(bc2(p4.z), v2, oacc[2]);
            oacc[3] = f2fma(bc2(p4.w), v2, oacc[3]);
        }
    }

    // normalize rows
    #pragma unroll
    for (int i = 0; i < 4; i++) {
        float inv = 1.0f / l_run[i];
        oacc[i] = f2mul(oacc[i], bc2(inv));
    }

    __syncthreads();  // everyone done with main-phase shared

    // stage O^T[ci][row]
    {
        float olo[4], ohi[4];
        #pragma unroll
        for (int i = 0; i < 4; i++) up2(oacc[i], olo[i], ohi[i]);
        *(float4*)&sOt[(2 * tx)     * TSTR + ty * 4] = make_float4(olo[0], olo[1], olo[2], olo[3]);
        *(float4*)&sOt[(2 * tx + 1) * TSTR + ty * 4] = make_float4(ohi[0], ohi[1], ohi[2], ohi[3]);
    }
    // load W_out [32][256]
    #pragma unroll
    for (int t = 0; t < 8; t++) {
        ((float4*)sWo)[tid + t * 256] = ((const float4*)Wout)[tid + t * 256];
    }
    __syncthreads();

    // ---- epilogue GEMM: out = x + sigma * (O @ W_out) ----
    // thread: rows ty*4..+4, cols {2tx + 32j}, j=0..7 (paired)
    uint64_t eacc[4][8];
    #pragma unroll
    for (int i = 0; i < 4; i++)
        #pragma unroll
        for (int j = 0; j < 8; j++) eacc[i][j] = 0ull;

    #pragma unroll 4
    for (int c = 0; c < CI_; c++) {
        float4 o4 = *(const float4*)&sOt[c * TSTR + ty * 4];
        uint64_t a0 = bc2(o4.x), a1 = bc2(o4.y), a2 = bc2(o4.z), a3 = bc2(o4.w);
        #pragma unroll
        for (int j = 0; j < 8; j++) {
            uint64_t w2 = *(const uint64_t*)&sWo[c * C_ + 2 * tx + 32 * j];
            eacc[0][j] = f2fma(a0, w2, eacc[0][j]);
            eacc[1][j] = f2fma(a1, w2, eacc[1][j]);
            eacc[2][j] = f2fma(a2, w2, eacc[2][j]);
            eacc[3][j] = f2fma(a3, w2, eacc[3][j]);
        }
    }

    const float sig = sigma_p[0];
    const uint64_t sig2 = bc2(sig);
    #pragma unroll
    for (int i = 0; i < 4; i++) {
        size_t rowoff = ((size_t)b * N_ + qb * BM + ty * 4 + i) * C_;
        #pragma unroll
        for (int j = 0; j < 8; j++) {
            size_t off = rowoff + 2 * tx + 32 * j;
            uint64_t x2 = *(const uint64_t*)&x[off];
            uint64_t r  = f2fma(sig2, eacc[i][j], x2);
            *(uint64_t*)&outp[off] = r;
        }
    }
}

// ---------------- launch ----------------
extern "C" void kernel_launch(void* const* d_in, const int* in_sizes, int n_in,
                              void* d_out, int out_size)
{
    (void)in_sizes; (void)n_in; (void)out_size;
    const float* x     = (const float*)d_in[0];
    const float* y     = (const float*)d_in[1];
    const float* Wfy   = (const float*)d_in[2];
    const float* Wgx   = (const float*)d_in[3];
    const float* Whx   = (const float*)d_in[4];
    const float* Wout  = (const float*)d_in[5];
    const float* sigma = (const float*)d_in[6];
    float* out = (float*)d_out;

    proj_kernel<<<dim3((B_ * N_) / BM, 3), 256>>>(x, y, Wfy, Wgx, Whx);
    attn_kernel<<<dim3(N_ / BM, B_), 256>>>(x, Wout, sigma, out);
}